// round 1
// baseline (speedup 1.0000x reference)
#include <cuda_runtime.h>
#include <cuda_bf16.h>
#include <math.h>

// Problem constants (fixed by the dataset)
#define MAXN 100000
#define MAXE 1600000
#define DIN  128
#define DH   128
#define DOUT 64
#define BN_EPS 1e-5f

// ---------------- scratch (no cudaMalloc allowed) ----------------
__device__ __align__(128) float g_mask[MAXE];
__device__ __align__(128) float g_outdeg[MAXN];
__device__ __align__(128) float g_indeg[MAXN];
__device__ __align__(128) float g_outnorm[MAXN];
__device__ __align__(128) float g_innorm[MAXN];
__device__ __align__(128) float g_x1[(size_t)MAXN * DH];
__device__ __align__(128) float g_agg1[(size_t)MAXN * DH];
__device__ __align__(128) float g_x2[(size_t)MAXN * DOUT];
__device__ __align__(128) float g_agg2[(size_t)MAXN * DOUT];
__device__ float g_sum1[DH], g_sq1[DH], g_a1[DH], g_c1[DH];
__device__ float g_sum2[DOUT], g_sq2[DOUT], g_a2[DOUT], g_c2[DOUT];
__device__ int   g_mode;   // 0=int32 mask, 1=float32 mask, 2=uint8 mask

// ---------------- mask dtype detection ----------------
// Scans the first `nwords` 32-bit words (guaranteed in-bounds for all three
// candidate encodings since nwords <= E/4). float32 masks contain only
// 0x00000000 / 0x3F800000; int32 masks only 0/1; uint8 masks produce words
// with multiple 0/1 bytes (values > 1, never 0x3F800000).
__global__ void detect_kernel(const unsigned* __restrict__ p, int nwords) {
    __shared__ int fl[2];
    if (threadIdx.x < 2) fl[threadIdx.x] = 0;
    __syncthreads();
    int lf = 0, lb = 0;
    for (int i = threadIdx.x; i < nwords; i += blockDim.x) {
        unsigned v = p[i];
        if (v == 0x3F800000u) lf = 1;
        else if (v > 1u)      lb = 1;
    }
    if (lf) fl[0] = 1;
    if (lb) fl[1] = 1;
    __syncthreads();
    if (threadIdx.x == 0) g_mode = fl[1] ? 2 : (fl[0] ? 1 : 0);
}

// ---------------- mask conversion + degree accumulation ----------------
__global__ void maskdeg_kernel(const void* __restrict__ mp,
                               const int* __restrict__ src,
                               const int* __restrict__ dst, int E) {
    int i = blockIdx.x * blockDim.x + threadIdx.x;
    if (i >= E) return;
    int mode = g_mode;
    bool keep;
    if (mode == 2)      keep = ((const unsigned char*)mp)[i] != 0;
    else if (mode == 1) keep = ((const float*)mp)[i] != 0.0f;
    else                keep = ((const int*)mp)[i] != 0;
    g_mask[i] = keep ? 1.0f : 0.0f;
    if (keep) {
        atomicAdd(&g_outdeg[src[i]], 1.0f);
        atomicAdd(&g_indeg[dst[i]], 1.0f);
    }
}

__global__ void norm_kernel(int N) {
    int i = blockIdx.x * blockDim.x + threadIdx.x;
    if (i < N) {
        g_outnorm[i] = rsqrtf(fmaxf(g_outdeg[i], 1.0f));
        g_innorm[i]  = rsqrtf(fmaxf(g_indeg[i], 1.0f));
    }
}

// ---------------- register-tiled fp32 GEMM, fused input transform --------
// Y[N,BLKN] = T(X)[N,128] @ W[128,BLKN]
// MODE 0: T(x[r,k]) = x[r,k] * outnorm[r]                      (layer 1)
// MODE 1: T(x[r,k]) = relu(x[r,k]*innorm[r]*a[k] + c[k]) * outnorm[r]  (layer 2,
//         folds h=agg*in_norm+b, BatchNorm, ReLU and the next out_norm scale)
template <int BLKN, int TN, int MODE>
__global__ __launch_bounds__(256) void gemm_kernel(
    const float* __restrict__ X, const float* __restrict__ W,
    float* __restrict__ Y,
    const float* __restrict__ outn, const float* __restrict__ inn,
    const float* __restrict__ a, const float* __restrict__ c, int N)
{
    constexpr int BM = 64, BK = 16, K = 128;
    __shared__ __align__(16) float As[BK][BM];   // transposed A tile
    __shared__ __align__(16) float Bs[BK][BLKN];
    const int tid  = threadIdx.x;
    const int tcol = tid & 31;   // 32 column groups
    const int trow = tid >> 5;   // 8 row groups of 8 rows
    const int row0 = blockIdx.x * BM;

    // A-tile loading role: one float4 per thread per k-chunk
    const int lr = tid >> 2;           // 0..63 local row
    const int lk = (tid & 3) * 4;      // 0,4,8,12 local k
    const int grow = row0 + lr;
    const bool rok = grow < N;
    const float rs = rok ? outn[grow] : 0.0f;
    float ri = 0.0f;
    if (MODE == 1 && rok) ri = inn[grow];

    float acc[8][TN];
#pragma unroll
    for (int i = 0; i < 8; i++)
#pragma unroll
        for (int j = 0; j < TN; j++) acc[i][j] = 0.0f;

    for (int kk = 0; kk < K; kk += BK) {
        float4 v = make_float4(0.f, 0.f, 0.f, 0.f);
        if (rok) v = *(const float4*)(X + (size_t)grow * K + kk + lk);
        if (MODE == 0) {
            v.x *= rs; v.y *= rs; v.z *= rs; v.w *= rs;
        } else {
            const int kb = kk + lk;
            v.x = fmaxf(fmaf(v.x * ri, a[kb + 0], c[kb + 0]), 0.0f) * rs;
            v.y = fmaxf(fmaf(v.y * ri, a[kb + 1], c[kb + 1]), 0.0f) * rs;
            v.z = fmaxf(fmaf(v.z * ri, a[kb + 2], c[kb + 2]), 0.0f) * rs;
            v.w = fmaxf(fmaf(v.w * ri, a[kb + 3], c[kb + 3]), 0.0f) * rs;
        }
        As[lk + 0][lr] = v.x; As[lk + 1][lr] = v.y;
        As[lk + 2][lr] = v.z; As[lk + 3][lr] = v.w;

        constexpr int NF4 = BK * BLKN / 4;
#pragma unroll
        for (int i = 0; i < NF4 / 256; i++) {
            int idx = tid + i * 256;
            int k   = idx / (BLKN / 4);
            int c4  = (idx % (BLKN / 4)) * 4;
            *(float4*)&Bs[k][c4] = *(const float4*)(W + (size_t)(kk + k) * BLKN + c4);
        }
        __syncthreads();
#pragma unroll
        for (int k = 0; k < BK; k++) {
            float ar[8];
#pragma unroll
            for (int i = 0; i < 8; i++) ar[i] = As[k][trow * 8 + i];
            float br[TN];
            if constexpr (TN == 4) {
                float4 b4 = *(const float4*)&Bs[k][tcol * 4];
                br[0] = b4.x; br[1] = b4.y; br[2] = b4.z; br[3] = b4.w;
            } else {
                float2 b2 = *(const float2*)&Bs[k][tcol * 2];
                br[0] = b2.x; br[1] = b2.y;
            }
#pragma unroll
            for (int i = 0; i < 8; i++)
#pragma unroll
                for (int j = 0; j < TN; j++)
                    acc[i][j] = fmaf(ar[i], br[j], acc[i][j]);
        }
        __syncthreads();
    }
#pragma unroll
    for (int i = 0; i < 8; i++) {
        int r = row0 + trow * 8 + i;
        if (r < N) {
            if constexpr (TN == 4) {
                float4 o = make_float4(acc[i][0], acc[i][1], acc[i][2], acc[i][3]);
                *(float4*)(Y + (size_t)r * BLKN + tcol * 4) = o;
            } else {
                float2 o = make_float2(acc[i][0], acc[i][1]);
                *(float2*)(Y + (size_t)r * BLKN + tcol * 2) = o;
            }
        }
    }
}

// ---------------- edge pass: warp per edge, vector RED scatter ----------
__global__ __launch_bounds__(256) void edge_kernel1(
    const int* __restrict__ src, const int* __restrict__ dst, int E) {
    int w = blockIdx.x * (blockDim.x >> 5) + (threadIdx.x >> 5);
    int lane = threadIdx.x & 31;
    if (w >= E) return;
    if (g_mask[w] == 0.0f) return;
    int sn = src[w], dn = dst[w];
    const float4* xr = (const float4*)(g_x1 + (size_t)sn * DH);
    float4 v = xr[lane];                         // 512B coalesced row gather
    float4* ar = (float4*)(g_agg1 + (size_t)dn * DH) + lane;
    asm volatile("red.global.add.v4.f32 [%0], {%1, %2, %3, %4};"
                 :: "l"(ar), "f"(v.x), "f"(v.y), "f"(v.z), "f"(v.w) : "memory");
}

__global__ __launch_bounds__(256) void edge_kernel2(
    const int* __restrict__ src, const int* __restrict__ dst, int E) {
    int w = blockIdx.x * (blockDim.x >> 5) + (threadIdx.x >> 5);
    int lane = threadIdx.x & 31;
    if (w >= E) return;
    if (g_mask[w] == 0.0f) return;
    int sn = src[w], dn = dst[w];
    const float2* xr = (const float2*)(g_x2 + (size_t)sn * DOUT);
    float2 v = xr[lane];                         // 256B coalesced row gather
    float2* ar = (float2*)(g_agg2 + (size_t)dn * DOUT) + lane;
    asm volatile("red.global.add.v2.f32 [%0], {%1, %2};"
                 :: "l"(ar), "f"(v.x), "f"(v.y) : "memory");
}

// ---------------- BN column statistics on h = agg*in_norm + b ----------
__global__ void stats_kernel(const float* __restrict__ agg,
                             const float* __restrict__ b,
                             float* __restrict__ colsum,
                             float* __restrict__ colsq, int N, int D) {
    int t = threadIdx.x;               // blockDim.x == D
    float bt = b[t];
    float s = 0.0f, q = 0.0f;
    for (int r = blockIdx.x; r < N; r += gridDim.x) {
        float h = fmaf(agg[(size_t)r * D + t], g_innorm[r], bt);
        s += h;
        q = fmaf(h, h, q);
    }
    atomicAdd(&colsum[t], s);
    atomicAdd(&colsq[t], q);
}

// a[t] = gamma*rsqrt(var+eps) ; c[t] = (b-mean)*a + beta
__global__ void fin_kernel(const float* __restrict__ colsum,
                           const float* __restrict__ colsq,
                           const float* __restrict__ gamma,
                           const float* __restrict__ beta,
                           const float* __restrict__ b,
                           float* __restrict__ a_out,
                           float* __restrict__ c_out, int N, int D) {
    int t = threadIdx.x;
    if (t < D) {
        float invn = 1.0f / (float)N;
        float mean = colsum[t] * invn;
        float var  = colsq[t] * invn - mean * mean;
        float istd = rsqrtf(var + BN_EPS);
        float a = gamma[t] * istd;
        a_out[t] = a;
        c_out[t] = (b[t] - mean) * a + beta[t];
    }
}

// ---------------- BN2 + log_softmax, warp per row ----------------
__global__ __launch_bounds__(256) void out_kernel(float* __restrict__ out, int N) {
    int row  = blockIdx.x * (blockDim.x >> 5) + (threadIdx.x >> 5);
    int lane = threadIdx.x & 31;
    if (row >= N) return;
    float ri = g_innorm[row];
    const float* ag = g_agg2 + (size_t)row * DOUT;
    float z0 = fmaf(ag[lane] * ri,      g_a2[lane],      g_c2[lane]);
    float z1 = fmaf(ag[lane + 32] * ri, g_a2[lane + 32], g_c2[lane + 32]);
    float m = fmaxf(z0, z1);
#pragma unroll
    for (int o = 16; o; o >>= 1) m = fmaxf(m, __shfl_xor_sync(0xFFFFFFFFu, m, o));
    float s = expf(z0 - m) + expf(z1 - m);
#pragma unroll
    for (int o = 16; o; o >>= 1) s += __shfl_xor_sync(0xFFFFFFFFu, s, o);
    float lse = m + logf(s);
    out[(size_t)row * DOUT + lane]      = z0 - lse;
    out[(size_t)row * DOUT + lane + 32] = z1 - lse;
}

// ---------------- host orchestration (graph-capturable) ----------------
extern "C" void kernel_launch(void* const* d_in, const int* in_sizes, int n_in,
                              void* d_out, int out_size) {
    const float* features = (const float*)d_in[0];
    const float* W1     = (const float*)d_in[1];
    const float* b1     = (const float*)d_in[2];
    const float* W2     = (const float*)d_in[3];
    const float* b2     = (const float*)d_in[4];
    const float* gamma1 = (const float*)d_in[5];
    const float* beta1  = (const float*)d_in[6];
    const float* gamma2 = (const float*)d_in[7];
    const float* beta2  = (const float*)d_in[8];
    const int*   esrc   = (const int*)d_in[9];
    const int*   edst   = (const int*)d_in[10];
    const void*  emask  = d_in[11];
    const int N = in_sizes[0] / DIN;
    const int E = in_sizes[9];
    float* out = (float*)d_out;
    cudaStream_t s = 0;

    // resolve scratch addresses
    void *p_outdeg, *p_indeg, *p_agg1, *p_agg2, *p_x1, *p_x2;
    void *p_outn, *p_inn, *p_sum1, *p_sq1, *p_a1, *p_c1, *p_sum2, *p_sq2, *p_a2, *p_c2;
    cudaGetSymbolAddress(&p_outdeg, g_outdeg);
    cudaGetSymbolAddress(&p_indeg,  g_indeg);
    cudaGetSymbolAddress(&p_agg1,   g_agg1);
    cudaGetSymbolAddress(&p_agg2,   g_agg2);
    cudaGetSymbolAddress(&p_x1,     g_x1);
    cudaGetSymbolAddress(&p_x2,     g_x2);
    cudaGetSymbolAddress(&p_outn,   g_outnorm);
    cudaGetSymbolAddress(&p_inn,    g_innorm);
    cudaGetSymbolAddress(&p_sum1,   g_sum1);
    cudaGetSymbolAddress(&p_sq1,    g_sq1);
    cudaGetSymbolAddress(&p_a1,     g_a1);
    cudaGetSymbolAddress(&p_c1,     g_c1);
    cudaGetSymbolAddress(&p_sum2,   g_sum2);
    cudaGetSymbolAddress(&p_sq2,    g_sq2);
    cudaGetSymbolAddress(&p_a2,     g_a2);
    cudaGetSymbolAddress(&p_c2,     g_c2);

    // zero accumulators every launch (deterministic)
    cudaMemsetAsync(p_outdeg, 0, (size_t)N * sizeof(float), s);
    cudaMemsetAsync(p_indeg,  0, (size_t)N * sizeof(float), s);
    cudaMemsetAsync(p_agg1,   0, (size_t)N * DH * sizeof(float), s);
    cudaMemsetAsync(p_agg2,   0, (size_t)N * DOUT * sizeof(float), s);
    cudaMemsetAsync(p_sum1,   0, DH * sizeof(float), s);
    cudaMemsetAsync(p_sq1,    0, DH * sizeof(float), s);
    cudaMemsetAsync(p_sum2,   0, DOUT * sizeof(float), s);
    cudaMemsetAsync(p_sq2,    0, DOUT * sizeof(float), s);

    // mask dtype detection + conversion + degrees + norms
    int nwords = E / 4 < 16384 ? E / 4 : 16384;
    detect_kernel<<<1, 256, 0, s>>>((const unsigned*)emask, nwords);
    maskdeg_kernel<<<(E + 255) / 256, 256, 0, s>>>(emask, esrc, edst, E);
    norm_kernel<<<(N + 255) / 256, 256, 0, s>>>(N);

    // layer 1: project (scaled) then gather/scatter
    gemm_kernel<DH, 4, 0><<<(N + 63) / 64, 256, 0, s>>>(
        features, W1, (float*)p_x1, (const float*)p_outn,
        nullptr, nullptr, nullptr, N);
    edge_kernel1<<<(E + 7) / 8, 256, 0, s>>>(esrc, edst, E);

    // BN1 stats on h1 = agg1*in_norm + b1 (computed on the fly)
    stats_kernel<<<1024, DH, 0, s>>>((const float*)p_agg1, b1,
                                     (float*)p_sum1, (float*)p_sq1, N, DH);
    fin_kernel<<<1, DH, 0, s>>>((const float*)p_sum1, (const float*)p_sq1,
                                gamma1, beta1, b1,
                                (float*)p_a1, (float*)p_c1, N, DH);

    // layer 2: fused (BN1+ReLU+out_norm) transform inside GEMM A-load
    gemm_kernel<DOUT, 2, 1><<<(N + 63) / 64, 256, 0, s>>>(
        (const float*)p_agg1, W2, (float*)p_x2, (const float*)p_outn,
        (const float*)p_inn, (const float*)p_a1, (const float*)p_c1, N);
    edge_kernel2<<<(E + 7) / 8, 256, 0, s>>>(esrc, edst, E);

    // BN2 stats + finalize
    stats_kernel<<<1024, DOUT, 0, s>>>((const float*)p_agg2, b2,
                                       (float*)p_sum2, (float*)p_sq2, N, DOUT);
    fin_kernel<<<1, DOUT, 0, s>>>((const float*)p_sum2, (const float*)p_sq2,
                                  gamma2, beta2, b2,
                                  (float*)p_a2, (float*)p_c2, N, DOUT);

    // BN2 + log_softmax -> output
    out_kernel<<<(N + 7) / 8, 256, 0, s>>>(out, N);
}

// round 3
// speedup vs baseline: 1.9608x; 1.9608x over previous
#include <cuda_runtime.h>
#include <cuda_bf16.h>
#include <math.h>

// Problem constants (fixed by the dataset)
#define MAXN 100000
#define MAXE 1600000
#define DIN  128
#define DH   128
#define DOUT 64
#define BN_EPS 1e-5f
#define SCAN_B 1024
#define MAXBLK ((MAXN + SCAN_B - 1) / SCAN_B)

// ---------------- scratch (no cudaMalloc allowed) ----------------
__device__ __align__(128) int   g_outcnt[MAXN];
__device__ __align__(128) int   g_incnt[MAXN];
__device__ __align__(128) int   g_rowstart[MAXN + 1];
__device__ __align__(128) int   g_cursor[MAXN];
__device__ __align__(128) int   g_srcs[MAXE];
__device__ __align__(128) int   g_bsum[MAXBLK];
__device__ __align__(128) int   g_boff[MAXBLK];
__device__ __align__(128) float g_outnorm[MAXN];
__device__ __align__(128) float g_innorm[MAXN];
__device__ __align__(128) float g_x1[(size_t)MAXN * DH];
__device__ __align__(128) float g_agg1[(size_t)MAXN * DH];
__device__ __align__(128) float g_x2[(size_t)MAXN * DOUT];
__device__ __align__(128) float g_agg2[(size_t)MAXN * DOUT];
__device__ float g_sum1[DH], g_sq1[DH], g_a1[DH], g_c1[DH];
__device__ float g_sum2[DOUT], g_sq2[DOUT], g_a2[DOUT], g_c2[DOUT];
__device__ int   g_mode;   // 0=int32 mask, 1=float32 mask, 2=uint8 mask

// ---------------- mask dtype detection ----------------
__global__ void detect_kernel(const unsigned* __restrict__ p, int nwords) {
    __shared__ int fl[2];
    if (threadIdx.x < 2) fl[threadIdx.x] = 0;
    __syncthreads();
    int lf = 0, lb = 0;
    for (int i = threadIdx.x; i < nwords; i += blockDim.x) {
        unsigned v = p[i];
        if (v == 0x3F800000u) lf = 1;
        else if (v > 1u)      lb = 1;
    }
    if (lf) fl[0] = 1;
    if (lb) fl[1] = 1;
    __syncthreads();
    if (threadIdx.x == 0) g_mode = fl[1] ? 2 : (fl[0] ? 1 : 0);
}

__device__ __forceinline__ bool edge_keep(const void* mp, int i) {
    int mode = g_mode;
    if (mode == 2)      return ((const unsigned char*)mp)[i] != 0;
    else if (mode == 1) return ((const float*)mp)[i] != 0.0f;
    else                return ((const int*)mp)[i] != 0;
}

// ---------------- degree counting (int) ----------------
__global__ void deg_kernel(const void* __restrict__ mp,
                           const int* __restrict__ src,
                           const int* __restrict__ dst, int E) {
    int i = blockIdx.x * blockDim.x + threadIdx.x;
    if (i >= E) return;
    if (edge_keep(mp, i)) {
        atomicAdd(&g_outcnt[src[i]], 1);
        atomicAdd(&g_incnt[dst[i]], 1);
    }
}

__global__ void norm_kernel(int N) {
    int i = blockIdx.x * blockDim.x + threadIdx.x;
    if (i < N) {
        g_outnorm[i] = rsqrtf(fmaxf((float)g_outcnt[i], 1.0f));
        g_innorm[i]  = rsqrtf(fmaxf((float)g_incnt[i], 1.0f));
    }
}

// ---------------- CSR build: two-level exclusive scan ----------------
__global__ __launch_bounds__(SCAN_B) void scan1_kernel(int N) {
    __shared__ int sh[SCAN_B];
    int i = blockIdx.x * SCAN_B + threadIdx.x;
    int v = (i < N) ? g_incnt[i] : 0;
    sh[threadIdx.x] = v;
    __syncthreads();
#pragma unroll
    for (int o = 1; o < SCAN_B; o <<= 1) {
        int t = (threadIdx.x >= o) ? sh[threadIdx.x - o] : 0;
        __syncthreads();
        sh[threadIdx.x] += t;
        __syncthreads();
    }
    if (i < N) g_rowstart[i] = sh[threadIdx.x] - v;   // exclusive
    if (threadIdx.x == SCAN_B - 1) g_bsum[blockIdx.x] = sh[threadIdx.x];
}

__global__ void scan2_kernel(int nb, int N) {
    if (threadIdx.x == 0) {
        int run = 0;
        for (int b = 0; b < nb; b++) { g_boff[b] = run; run += g_bsum[b]; }
        g_rowstart[N] = run;
    }
}

__global__ void scan3_kernel(int N) {
    int i = blockIdx.x * blockDim.x + threadIdx.x;
    if (i < N) {
        int r = g_rowstart[i] + g_boff[i >> 10];
        g_rowstart[i] = r;
        g_cursor[i]   = r;
    }
}

__global__ void scatter_kernel(const void* __restrict__ mp,
                               const int* __restrict__ src,
                               const int* __restrict__ dst, int E) {
    int i = blockIdx.x * blockDim.x + threadIdx.x;
    if (i >= E) return;
    if (edge_keep(mp, i)) {
        int p = atomicAdd(&g_cursor[dst[i]], 1);
        g_srcs[p] = src[i];
    }
}

// ---------------- register-tiled fp32 GEMM, fused input transform --------
// Y[N,BLKN] = T(X)[N,128] @ W[128,BLKN]
// MODE 0: T(x[r,k]) = x[r,k] * outnorm[r]
// MODE 1: T(x[r,k]) = relu(x[r,k]*innorm[r]*a[k] + c[k]) * outnorm[r]
template <int BLKN, int TN, int MODE>
__global__ __launch_bounds__(256) void gemm_kernel(
    const float* __restrict__ X, const float* __restrict__ W,
    float* __restrict__ Y,
    const float* __restrict__ outn, const float* __restrict__ inn,
    const float* __restrict__ a, const float* __restrict__ c, int N)
{
    constexpr int BM = 64, BK = 16, K = 128;
    __shared__ __align__(16) float As[BK][BM];
    __shared__ __align__(16) float Bs[BK][BLKN];
    const int tid  = threadIdx.x;
    const int tcol = tid & 31;
    const int trow = tid >> 5;
    const int row0 = blockIdx.x * BM;

    const int lr = tid >> 2;
    const int lk = (tid & 3) * 4;
    const int grow = row0 + lr;
    const bool rok = grow < N;
    const float rs = rok ? outn[grow] : 0.0f;
    float ri = 0.0f;
    if (MODE == 1 && rok) ri = inn[grow];

    float acc[8][TN];
#pragma unroll
    for (int i = 0; i < 8; i++)
#pragma unroll
        for (int j = 0; j < TN; j++) acc[i][j] = 0.0f;

    for (int kk = 0; kk < K; kk += BK) {
        float4 v = make_float4(0.f, 0.f, 0.f, 0.f);
        if (rok) v = *(const float4*)(X + (size_t)grow * K + kk + lk);
        if (MODE == 0) {
            v.x *= rs; v.y *= rs; v.z *= rs; v.w *= rs;
        } else {
            const int kb = kk + lk;
            v.x = fmaxf(fmaf(v.x * ri, a[kb + 0], c[kb + 0]), 0.0f) * rs;
            v.y = fmaxf(fmaf(v.y * ri, a[kb + 1], c[kb + 1]), 0.0f) * rs;
            v.z = fmaxf(fmaf(v.z * ri, a[kb + 2], c[kb + 2]), 0.0f) * rs;
            v.w = fmaxf(fmaf(v.w * ri, a[kb + 3], c[kb + 3]), 0.0f) * rs;
        }
        As[lk + 0][lr] = v.x; As[lk + 1][lr] = v.y;
        As[lk + 2][lr] = v.z; As[lk + 3][lr] = v.w;

        constexpr int NF4 = BK * BLKN / 4;
#pragma unroll
        for (int i = 0; i < NF4 / 256; i++) {
            int idx = tid + i * 256;
            int k   = idx / (BLKN / 4);
            int c4  = (idx % (BLKN / 4)) * 4;
            *(float4*)&Bs[k][c4] = *(const float4*)(W + (size_t)(kk + k) * BLKN + c4);
        }
        __syncthreads();
#pragma unroll
        for (int k = 0; k < BK; k++) {
            float ar[8];
#pragma unroll
            for (int i = 0; i < 8; i++) ar[i] = As[k][trow * 8 + i];
            float br[TN];
            if constexpr (TN == 4) {
                float4 b4 = *(const float4*)&Bs[k][tcol * 4];
                br[0] = b4.x; br[1] = b4.y; br[2] = b4.z; br[3] = b4.w;
            } else {
                float2 b2 = *(const float2*)&Bs[k][tcol * 2];
                br[0] = b2.x; br[1] = b2.y;
            }
#pragma unroll
            for (int i = 0; i < 8; i++)
#pragma unroll
                for (int j = 0; j < TN; j++)
                    acc[i][j] = fmaf(ar[i], br[j], acc[i][j]);
        }
        __syncthreads();
    }
#pragma unroll
    for (int i = 0; i < 8; i++) {
        int r = row0 + trow * 8 + i;
        if (r < N) {
            if constexpr (TN == 4) {
                float4 o = make_float4(acc[i][0], acc[i][1], acc[i][2], acc[i][3]);
                *(float4*)(Y + (size_t)r * BLKN + tcol * 4) = o;
            } else {
                float2 o = make_float2(acc[i][0], acc[i][1]);
                *(float2*)(Y + (size_t)r * BLKN + tcol * 2) = o;
            }
        }
    }
}

// ---------------- CSR aggregation: warp per node, register accumulation --
// Each warp owns one destination node; lanes cover the feature row.
// No atomics: each agg row is written exactly once.
__global__ __launch_bounds__(256) void agg_kernel1(
    const float* __restrict__ X, float* __restrict__ A, int N) {
    int n = blockIdx.x * (blockDim.x >> 5) + (threadIdx.x >> 5);
    int lane = threadIdx.x & 31;
    if (n >= N) return;
    int e   = g_rowstart[n];
    int end = g_rowstart[n + 1];
    float4 acc = make_float4(0.f, 0.f, 0.f, 0.f);
    for (; e + 1 < end; e += 2) {
        int s0 = g_srcs[e], s1 = g_srcs[e + 1];
        float4 v0 = ((const float4*)(X + (size_t)s0 * DH))[lane];
        float4 v1 = ((const float4*)(X + (size_t)s1 * DH))[lane];
        acc.x += v0.x; acc.y += v0.y; acc.z += v0.z; acc.w += v0.w;
        acc.x += v1.x; acc.y += v1.y; acc.z += v1.z; acc.w += v1.w;
    }
    if (e < end) {
        int s0 = g_srcs[e];
        float4 v0 = ((const float4*)(X + (size_t)s0 * DH))[lane];
        acc.x += v0.x; acc.y += v0.y; acc.z += v0.z; acc.w += v0.w;
    }
    ((float4*)(A + (size_t)n * DH))[lane] = acc;
}

__global__ __launch_bounds__(256) void agg_kernel2(
    const float* __restrict__ X, float* __restrict__ A, int N) {
    int n = blockIdx.x * (blockDim.x >> 5) + (threadIdx.x >> 5);
    int lane = threadIdx.x & 31;
    if (n >= N) return;
    int e   = g_rowstart[n];
    int end = g_rowstart[n + 1];
    float2 acc = make_float2(0.f, 0.f);
    for (; e + 3 < end; e += 4) {
        int s0 = g_srcs[e], s1 = g_srcs[e + 1], s2 = g_srcs[e + 2], s3 = g_srcs[e + 3];
        float2 v0 = ((const float2*)(X + (size_t)s0 * DOUT))[lane];
        float2 v1 = ((const float2*)(X + (size_t)s1 * DOUT))[lane];
        float2 v2 = ((const float2*)(X + (size_t)s2 * DOUT))[lane];
        float2 v3 = ((const float2*)(X + (size_t)s3 * DOUT))[lane];
        acc.x += v0.x; acc.y += v0.y;
        acc.x += v1.x; acc.y += v1.y;
        acc.x += v2.x; acc.y += v2.y;
        acc.x += v3.x; acc.y += v3.y;
    }
    for (; e < end; e++) {
        int s0 = g_srcs[e];
        float2 v0 = ((const float2*)(X + (size_t)s0 * DOUT))[lane];
        acc.x += v0.x; acc.y += v0.y;
    }
    ((float2*)(A + (size_t)n * DOUT))[lane] = acc;
}

// ---------------- BN column statistics on h = agg*in_norm + b ----------
__global__ void stats_kernel(const float* __restrict__ agg,
                             const float* __restrict__ b,
                             float* __restrict__ colsum,
                             float* __restrict__ colsq, int N, int D) {
    int t = threadIdx.x;
    float bt = b[t];
    float s = 0.0f, q = 0.0f;
    for (int r = blockIdx.x; r < N; r += gridDim.x) {
        float h = fmaf(agg[(size_t)r * D + t], g_innorm[r], bt);
        s += h;
        q = fmaf(h, h, q);
    }
    atomicAdd(&colsum[t], s);
    atomicAdd(&colsq[t], q);
}

__global__ void fin_kernel(const float* __restrict__ colsum,
                           const float* __restrict__ colsq,
                           const float* __restrict__ gamma,
                           const float* __restrict__ beta,
                           const float* __restrict__ b,
                           float* __restrict__ a_out,
                           float* __restrict__ c_out, int N, int D) {
    int t = threadIdx.x;
    if (t < D) {
        float invn = 1.0f / (float)N;
        float mean = colsum[t] * invn;
        float var  = colsq[t] * invn - mean * mean;
        float istd = rsqrtf(var + BN_EPS);
        float a = gamma[t] * istd;
        a_out[t] = a;
        c_out[t] = (b[t] - mean) * a + beta[t];
    }
}

// ---------------- BN2 + log_softmax, warp per row ----------------
__global__ __launch_bounds__(256) void out_kernel(float* __restrict__ out, int N) {
    int row  = blockIdx.x * (blockDim.x >> 5) + (threadIdx.x >> 5);
    int lane = threadIdx.x & 31;
    if (row >= N) return;
    float ri = g_innorm[row];
    const float* ag = g_agg2 + (size_t)row * DOUT;
    float z0 = fmaf(ag[lane] * ri,      g_a2[lane],      g_c2[lane]);
    float z1 = fmaf(ag[lane + 32] * ri, g_a2[lane + 32], g_c2[lane + 32]);
    float m = fmaxf(z0, z1);
#pragma unroll
    for (int o = 16; o; o >>= 1) m = fmaxf(m, __shfl_xor_sync(0xFFFFFFFFu, m, o));
    float s = expf(z0 - m) + expf(z1 - m);
#pragma unroll
    for (int o = 16; o; o >>= 1) s += __shfl_xor_sync(0xFFFFFFFFu, s, o);
    float lse = m + logf(s);
    out[(size_t)row * DOUT + lane]      = z0 - lse;
    out[(size_t)row * DOUT + lane + 32] = z1 - lse;
}

// ---------------- host orchestration (graph-capturable) ----------------
extern "C" void kernel_launch(void* const* d_in, const int* in_sizes, int n_in,
                              void* d_out, int out_size) {
    const float* features = (const float*)d_in[0];
    const float* W1     = (const float*)d_in[1];
    const float* b1     = (const float*)d_in[2];
    const float* W2     = (const float*)d_in[3];
    const float* b2     = (const float*)d_in[4];
    const float* gamma1 = (const float*)d_in[5];
    const float* beta1  = (const float*)d_in[6];
    const float* gamma2 = (const float*)d_in[7];
    const float* beta2  = (const float*)d_in[8];
    const int*   esrc   = (const int*)d_in[9];
    const int*   edst   = (const int*)d_in[10];
    const void*  emask  = d_in[11];
    const int N = in_sizes[0] / DIN;
    const int E = in_sizes[9];
    float* out = (float*)d_out;
    cudaStream_t s = 0;

    void *p_outcnt, *p_incnt, *p_x1, *p_x2, *p_agg1, *p_agg2;
    void *p_outn, *p_inn, *p_sum1, *p_sq1, *p_a1, *p_c1, *p_sum2, *p_sq2, *p_a2, *p_c2;
    cudaGetSymbolAddress(&p_outcnt, g_outcnt);
    cudaGetSymbolAddress(&p_incnt,  g_incnt);
    cudaGetSymbolAddress(&p_x1,     g_x1);
    cudaGetSymbolAddress(&p_x2,     g_x2);
    cudaGetSymbolAddress(&p_agg1,   g_agg1);
    cudaGetSymbolAddress(&p_agg2,   g_agg2);
    cudaGetSymbolAddress(&p_outn,   g_outnorm);
    cudaGetSymbolAddress(&p_inn,    g_innorm);
    cudaGetSymbolAddress(&p_sum1,   g_sum1);
    cudaGetSymbolAddress(&p_sq1,    g_sq1);
    cudaGetSymbolAddress(&p_a1,     g_a1);
    cudaGetSymbolAddress(&p_c1,     g_c1);
    cudaGetSymbolAddress(&p_sum2,   g_sum2);
    cudaGetSymbolAddress(&p_sq2,    g_sq2);
    cudaGetSymbolAddress(&p_a2,     g_a2);
    cudaGetSymbolAddress(&p_c2,     g_c2);

    // zero counters (small; agg arrays no longer need zeroing)
    cudaMemsetAsync(p_outcnt, 0, (size_t)N * sizeof(int), s);
    cudaMemsetAsync(p_incnt,  0, (size_t)N * sizeof(int), s);
    cudaMemsetAsync(p_sum1,   0, DH * sizeof(float), s);
    cudaMemsetAsync(p_sq1,    0, DH * sizeof(float), s);
    cudaMemsetAsync(p_sum2,   0, DOUT * sizeof(float), s);
    cudaMemsetAsync(p_sq2,    0, DOUT * sizeof(float), s);

    // mask detection, degrees, norms
    int nwords = E / 4 < 16384 ? E / 4 : 16384;
    detect_kernel<<<1, 256, 0, s>>>((const unsigned*)emask, nwords);
    deg_kernel<<<(E + 255) / 256, 256, 0, s>>>(emask, esrc, edst, E);
    norm_kernel<<<(N + 255) / 256, 256, 0, s>>>(N);

    // CSR build (by destination)
    int nb = (N + SCAN_B - 1) / SCAN_B;
    scan1_kernel<<<nb, SCAN_B, 0, s>>>(N);
    scan2_kernel<<<1, 32, 0, s>>>(nb, N);
    scan3_kernel<<<(N + 255) / 256, 256, 0, s>>>(N);
    scatter_kernel<<<(E + 255) / 256, 256, 0, s>>>(emask, esrc, edst, E);

    // layer 1: project (scaled) then CSR aggregate
    gemm_kernel<DH, 4, 0><<<(N + 63) / 64, 256, 0, s>>>(
        features, W1, (float*)p_x1, (const float*)p_outn,
        nullptr, nullptr, nullptr, N);
    agg_kernel1<<<(N + 7) / 8, 256, 0, s>>>((const float*)p_x1, (float*)p_agg1, N);

    // BN1 stats
    stats_kernel<<<1024, DH, 0, s>>>((const float*)p_agg1, b1,
                                     (float*)p_sum1, (float*)p_sq1, N, DH);
    fin_kernel<<<1, DH, 0, s>>>((const float*)p_sum1, (const float*)p_sq1,
                                gamma1, beta1, b1,
                                (float*)p_a1, (float*)p_c1, N, DH);

    // layer 2
    gemm_kernel<DOUT, 2, 1><<<(N + 63) / 64, 256, 0, s>>>(
        (const float*)p_agg1, W2, (float*)p_x2, (const float*)p_outn,
        (const float*)p_inn, (const float*)p_a1, (const float*)p_c1, N);
    agg_kernel2<<<(N + 7) / 8, 256, 0, s>>>((const float*)p_x2, (float*)p_agg2, N);

    // BN2 + output
    stats_kernel<<<1024, DOUT, 0, s>>>((const float*)p_agg2, b2,
                                       (float*)p_sum2, (float*)p_sq2, N, DOUT);
    fin_kernel<<<1, DOUT, 0, s>>>((const float*)p_sum2, (const float*)p_sq2,
                                  gamma2, beta2, b2,
                                  (float*)p_a2, (float*)p_c2, N, DOUT);
    out_kernel<<<(N + 7) / 8, 256, 0, s>>>(out, N);
}